// round 8
// baseline (speedup 1.0000x reference)
#include <cuda_runtime.h>
#include <cuda_fp8.h>
#include <math.h>
#include <stdint.h>

// ---------------- problem constants ----------------
#define N_ROWS 16384
#define D2     1024
#define KSYM   8192
#define BM     128            // rows per CTA (blockIdx.y)
#define BN     128            // symbol cols per CTA (blockIdx.x)
#define BK     64             // k-chunk per stage (e4m3: 64B/row)
#define NCHUNK (D2 / BK)      // 16
#define RECORDS 256           // per-row top2 records = 64 col tiles * 4 warpN
#define MARGIN 16.0f
#define MAXCAND 24
#define GWSCALE 64.0f
#define GWINV   0.015625f

// output packing (reference tuple order, flattened, float32)
#define ZQ_OFF   0ULL
#define LOSS_OFF 16777216ULL
#define MIDX_OFF 16777217ULL
#define NCB_OFF  16793601ULL
#define NCS_OFF  25182209ULL
#define NEA_OFF  25190401ULL

// smem stage layout: four e4m3 segments, 128 rows x 64B each (quad-permuted)
#define SEG_Z   0
#define SEG_CB  8192
#define SEG_C   16384
#define SEG_GW  24576
#define STAGE   32768
#define NSTAGE  3
#define SMEM_BYTES (NSTAGE * STAGE)   // 98304

// ---------------- scratch (device globals, no allocation) ----------------
__device__ float  g_cnorm[KSYM];
__device__ float  g_top2v[(size_t)N_ROWS * RECORDS * 2];
__device__ int    g_top2i[(size_t)N_ROWS * RECORDS * 2];
__device__ int    g_midx[N_ROWS];
__device__ int    g_counts[KSYM];
__device__ double g_loss;
__device__ float  g_cs[KSYM];
// quad-permuted e4m3 operand copies (uint32 = 4 elems), 256 words/row
__device__ uint32_t g_zp[(size_t)N_ROWS * 256];
__device__ uint32_t g_cbp[(size_t)KSYM * 256];
__device__ uint32_t g_ctxp[(size_t)N_ROWS * 256];
__device__ uint32_t g_gwp[(size_t)KSYM * 256];   // gate_w * 64

// ---------------- helpers ----------------
__device__ __forceinline__ uint32_t smem_to_u32(const void* p) {
    uint32_t a;
    asm("{ .reg .u64 t; cvta.to.shared.u64 t, %1; cvt.u32.u64 %0, t; }" : "=r"(a) : "l"(p));
    return a;
}
__device__ __forceinline__ float tanh_approx(float x) {
    float y; asm("tanh.approx.f32 %0, %1;" : "=f"(y) : "f"(x)); return y;
}
__device__ __forceinline__ void cp16(uint32_t dst, const void* src) {
    asm volatile("cp.async.cg.shared.global [%0], [%1], 16;" :: "r"(dst), "l"(src));
}
__device__ __forceinline__ uint4 lds128(uint32_t addr) {
    uint4 v;
    asm volatile("ld.shared.v4.b32 {%0,%1,%2,%3}, [%4];"
        : "=r"(v.x), "=r"(v.y), "=r"(v.z), "=r"(v.w) : "r"(addr));
    return v;
}
__device__ __forceinline__ void mma_e4m3(float* d, const uint32_t* a, const uint32_t* b) {
    asm volatile(
        "mma.sync.aligned.m16n8k32.row.col.f32.e4m3.e4m3.f32 "
        "{%0,%1,%2,%3}, {%4,%5,%6,%7}, {%8,%9}, {%0,%1,%2,%3};"
        : "+f"(d[0]), "+f"(d[1]), "+f"(d[2]), "+f"(d[3])
        : "r"(a[0]), "r"(a[1]), "r"(a[2]), "r"(a[3]), "r"(b[0]), "r"(b[1]));
}

// quad q (k=4q..4q+3) -> permuted word slot within row (256 words/row).
// chunk c = q>>4 (64 k each); within chunk: b = bit3, qq = q&7;
// slot = c*16 + (qq&3)*4 + b*2 + (qq>>2)
__device__ __forceinline__ int qslot(int q) {
    int c = q >> 4;
    int q16 = q & 15;
    int b = q16 >> 3, qq = q16 & 7;
    return c * 16 + (qq & 3) * 4 + b * 2 + (qq >> 2);
}
__device__ __forceinline__ uint32_t pack4_e4m3(float a, float b, float c, float d) {
    uint32_t r = (uint32_t)__nv_cvt_float_to_fp8(a, __NV_SATFINITE, __NV_E4M3);
    r |= (uint32_t)__nv_cvt_float_to_fp8(b, __NV_SATFINITE, __NV_E4M3) << 8;
    r |= (uint32_t)__nv_cvt_float_to_fp8(c, __NV_SATFINITE, __NV_E4M3) << 16;
    r |= (uint32_t)__nv_cvt_float_to_fp8(d, __NV_SATFINITE, __NV_E4M3) << 24;
    return r;
}

// ---------------- 0. permute+convert prep kernels ----------------
__global__ void perm_z_kernel(const float* __restrict__ zr, const float* __restrict__ zi) {
    size_t total = (size_t)N_ROWS * 256;
    size_t stride = (size_t)gridDim.x * blockDim.x;
    for (size_t i = (size_t)blockIdx.x * blockDim.x + threadIdx.x; i < total; i += stride) {
        int n = (int)(i >> 8), q = (int)(i & 255);
        int k = 4 * q;
        const float* src = (k < 512) ? zr + (size_t)n * 512 + k : zi + (size_t)n * 512 + k - 512;
        g_zp[(size_t)n * 256 + qslot(q)] = pack4_e4m3(src[0], src[1], src[2], src[3]);
    }
}
__global__ void perm_cb_kernel(const float* __restrict__ cb) {
    size_t total = (size_t)KSYM * 256;
    size_t stride = (size_t)gridDim.x * blockDim.x;
    for (size_t i = (size_t)blockIdx.x * blockDim.x + threadIdx.x; i < total; i += stride) {
        int n = (int)(i >> 8), q = (int)(i & 255);
        const float* src = cb + (size_t)n * 1024 + 4 * q;
        g_cbp[(size_t)n * 256 + qslot(q)] = pack4_e4m3(src[0], src[1], src[2], src[3]);
    }
}
__global__ void perm_ctx_kernel(const float* __restrict__ cr, const float* __restrict__ ci) {
    size_t total = (size_t)N_ROWS * 256;
    size_t stride = (size_t)gridDim.x * blockDim.x;
    for (size_t i = (size_t)blockIdx.x * blockDim.x + threadIdx.x; i < total; i += stride) {
        int n = (int)(i >> 8), q = (int)(i & 255);
        int k = 4 * q;
        const float* src = (k < 512) ? cr + (size_t)n * 512 + k : ci + (size_t)n * 512 + k - 512;
        g_ctxp[(size_t)n * 256 + qslot(q)] = pack4_e4m3(src[0], src[1], src[2], src[3]);
    }
}
__global__ void perm_gw_kernel(const float* __restrict__ gw) {
    size_t total = (size_t)KSYM * 256;
    size_t stride = (size_t)gridDim.x * blockDim.x;
    for (size_t i = (size_t)blockIdx.x * blockDim.x + threadIdx.x; i < total; i += stride) {
        int n = (int)(i >> 8), q = (int)(i & 255);
        const float* src = gw + (size_t)n * 1024 + 4 * q;
        g_gwp[(size_t)n * 256 + qslot(q)] =
            pack4_e4m3(src[0] * GWSCALE, src[1] * GWSCALE, src[2] * GWSCALE, src[3] * GWSCALE);
    }
}

// ---------------- 1. codebook row norms (fp64 accumulate) ----------------
__global__ void prep_cnorm_kernel(const float* __restrict__ codebook) {
    int k = blockIdx.x;
    const float* row = codebook + (size_t)k * D2;
    double s = 0.0;
    for (int t = threadIdx.x; t < D2; t += 256) { double v = (double)row[t]; s += v * v; }
    __shared__ double sh[256];
    sh[threadIdx.x] = s; __syncthreads();
    for (int o = 128; o > 0; o >>= 1) { if (threadIdx.x < o) sh[threadIdx.x] += sh[threadIdx.x + o]; __syncthreads(); }
    if (threadIdx.x == 0) g_cnorm[k] = (float)sh[0];
}

// ---------------- 2. init ----------------
__global__ void init_kernel(const float* __restrict__ embed_avg, float* __restrict__ out) {
    size_t total = (size_t)KSYM * D2;
    size_t stride = (size_t)gridDim.x * blockDim.x;
    size_t j = (size_t)blockIdx.x * blockDim.x + threadIdx.x;
    for (size_t i = j; i < total; i += stride) out[NEA_OFF + i] = 0.99f * embed_avg[i];
    if (j < KSYM) g_counts[j] = 0;
    if (j == 0) g_loss = 0.0;
}

// ---------------- 3. fused dual-GEMM score kernel (e4m3) ----------------
// 512 threads, 16 warps: warp grid 4(M) x 4(N), warp tile 32x32, CTA tile 128x128.
__global__ __launch_bounds__(512, 1)
void score_mma_kernel(const int* __restrict__ prev_idx,
                      const float* __restrict__ adjacency,
                      const float* __restrict__ gate_b) {
    extern __shared__ char smem[];
    const uint32_t sbu = smem_to_u32(smem);
    const int tid   = threadIdx.x;
    const int wid   = tid >> 5;
    const int lane  = tid & 31;
    const int g     = lane >> 2;
    const int tig   = lane & 3;
    const int warpM = wid >> 2;
    const int warpN = wid & 3;
    const int rowBase = blockIdx.y * BM;
    const int cbase   = blockIdx.x * BN;

    // ---- stage loader: 4 x 16B per thread, all contiguous ----
    auto load_stage = [&](int c, int buf) {
        const uint32_t bb = sbu + (uint32_t)buf * STAGE;
        int r = tid >> 2, qq = tid & 3;
        uint32_t so = (uint32_t)(r * 64 + qq * 16);
        size_t gr = (size_t)(rowBase + r) * 256 + c * 16 + qq * 4;
        size_t gc = (size_t)(cbase + r) * 256 + c * 16 + qq * 4;
        cp16(bb + SEG_Z + so, g_zp + gr);
        cp16(bb + SEG_CB + so, g_cbp + gc);
        cp16(bb + SEG_C + so, g_ctxp + gr);
        cp16(bb + SEG_GW + so, g_gwp + gc);
        asm volatile("cp.async.commit_group;" ::: "memory");
    };

    float accd[2][4][4], accg[2][4][4];
#pragma unroll
    for (int mt = 0; mt < 2; mt++)
#pragma unroll
        for (int nt = 0; nt < 4; nt++)
#pragma unroll
            for (int e = 0; e < 4; e++) { accd[mt][nt][e] = 0.f; accg[mt][nt][e] = 0.f; }

    uint32_t aZ[4], aB[4], aC[4], aG[4];
#pragma unroll
    for (int s = 0; s < 4; s++) {
        aZ[s] = SEG_Z  + (uint32_t)(warpM * 32 + g + 8 * s) * 64 + tig * 16;
        aB[s] = SEG_CB + (uint32_t)(warpN * 32 + g + 8 * s) * 64 + tig * 16;
        aC[s] = SEG_C  + (uint32_t)(warpM * 32 + g + 8 * s) * 64 + tig * 16;
        aG[s] = SEG_GW + (uint32_t)(warpN * 32 + g + 8 * s) * 64 + tig * 16;
    }

    load_stage(0, 0);
    load_stage(1, 1);

    int buf = 0;
    for (int c = 0; c < NCHUNK; ++c) {
        if (c + 1 < NCHUNK) asm volatile("cp.async.wait_group 1;" ::: "memory");
        else                asm volatile("cp.async.wait_group 0;" ::: "memory");
        __syncthreads();
        if (c + 2 < NCHUNK) {
            int nb = buf + 2; if (nb >= NSTAGE) nb -= NSTAGE;
            load_stage(c + 2, nb);
        }
        const uint32_t bb = sbu + (uint32_t)buf * STAGE;

        // ---- dot GEMM (e4m3): 2 k32-steps ----
        {
            uint32_t ax[4][4], bx[4][4];
#pragma unroll
            for (int s = 0; s < 4; s++) {
                uint4 vz = lds128(bb + aZ[s]);
                ax[s][0] = vz.x; ax[s][1] = vz.y; ax[s][2] = vz.z; ax[s][3] = vz.w;
                uint4 vb = lds128(bb + aB[s]);
                bx[s][0] = vb.x; bx[s][1] = vb.y; bx[s][2] = vb.z; bx[s][3] = vb.w;
            }
#pragma unroll
            for (int t = 0; t < 2; t++) {
                uint32_t af0[4] = {ax[0][2*t], ax[1][2*t], ax[0][2*t+1], ax[1][2*t+1]};
                uint32_t af1[4] = {ax[2][2*t], ax[3][2*t], ax[2][2*t+1], ax[3][2*t+1]};
#pragma unroll
                for (int nt = 0; nt < 4; nt++) {
                    uint32_t bf2[2] = {bx[nt][2*t], bx[nt][2*t+1]};
                    mma_e4m3(accd[0][nt], af0, bf2);
                    mma_e4m3(accd[1][nt], af1, bf2);
                }
            }
        }
        // ---- gate GEMM (e4m3): 2 k32-steps ----
        {
            uint32_t ax[4][4], bx[4][4];
#pragma unroll
            for (int s = 0; s < 4; s++) {
                uint4 vc = lds128(bb + aC[s]);
                ax[s][0] = vc.x; ax[s][1] = vc.y; ax[s][2] = vc.z; ax[s][3] = vc.w;
                uint4 vw = lds128(bb + aG[s]);
                bx[s][0] = vw.x; bx[s][1] = vw.y; bx[s][2] = vw.z; bx[s][3] = vw.w;
            }
#pragma unroll
            for (int t = 0; t < 2; t++) {
                uint32_t af0[4] = {ax[0][2*t], ax[1][2*t], ax[0][2*t+1], ax[1][2*t+1]};
                uint32_t af1[4] = {ax[2][2*t], ax[3][2*t], ax[2][2*t+1], ax[3][2*t+1]};
#pragma unroll
                for (int nt = 0; nt < 4; nt++) {
                    uint32_t bf2[2] = {bx[nt][2*t], bx[nt][2*t+1]};
                    mma_e4m3(accg[0][nt], af0, bf2);
                    mma_e4m3(accg[1][nt], af1, bf2);
                }
            }
        }
        buf++; if (buf >= NSTAGE) buf = 0;
    }

    // ---- epilogue: bias + per-row top-2 ----
    float cnv[4][2], gbv[4][2];
#pragma unroll
    for (int nt = 0; nt < 4; nt++)
#pragma unroll
        for (int e = 0; e < 2; e++) {
            int col = cbase + warpN * 32 + nt * 8 + 2 * tig + e;
            cnv[nt][e] = g_cnorm[col];
            gbv[nt][e] = gate_b[col];
        }

    const float INF = __int_as_float(0x7f800000);
#pragma unroll
    for (int mt = 0; mt < 2; mt++)
#pragma unroll
        for (int hi = 0; hi < 2; hi++) {
            int rowg = rowBase + warpM * 32 + mt * 16 + hi * 8 + g;
            const float* adjr = adjacency + (size_t)prev_idx[rowg] * KSYM;
            float V1 = INF, V2 = INF;
            int   I1 = 0x7fffffff, I2 = 0x7fffffff;
#pragma unroll
            for (int nt = 0; nt < 4; nt++)
#pragma unroll
                for (int e = 0; e < 2; e++) {
                    int col = cbase + warpN * 32 + nt * 8 + 2 * tig + e;
                    float dot = accd[mt][nt][hi * 2 + e];
                    float gt  = accg[mt][nt][hi * 2 + e];
                    float adj = __ldg(adjr + col);
                    float sig = 1.f / (1.f + __expf(-adj));
                    float th  = tanh_approx(fmaf(gt, GWINV, gbv[nt][e]));
                    float s = fmaf(-2.f, dot, cnv[nt][e]) - 0.8f * sig * fmaf(0.5f, th, 1.f);
                    if (s < V1 || (s == V1 && col < I1)) { V2 = V1; I2 = I1; V1 = s; I1 = col; }
                    else if (s < V2 || (s == V2 && col < I2)) { V2 = s; I2 = col; }
                }
#pragma unroll
            for (int off = 1; off <= 2; off <<= 1) {
                float ov1 = __shfl_xor_sync(0xffffffffu, V1, off);
                int   oi1 = __shfl_xor_sync(0xffffffffu, I1, off);
                float ov2 = __shfl_xor_sync(0xffffffffu, V2, off);
                int   oi2 = __shfl_xor_sync(0xffffffffu, I2, off);
                if (ov1 < V1 || (ov1 == V1 && oi1 < I1)) {
                    float nv2; int ni2;
                    if (V1 < ov2 || (V1 == ov2 && I1 < oi2)) { nv2 = V1; ni2 = I1; }
                    else { nv2 = ov2; ni2 = oi2; }
                    V1 = ov1; I1 = oi1; V2 = nv2; I2 = ni2;
                } else if (ov1 < V2 || (ov1 == V2 && oi1 < I2)) {
                    V2 = ov1; I2 = oi1;
                }
            }
            if (tig == 0) {
                size_t o = ((size_t)rowg * RECORDS + blockIdx.x * 4 + warpN) * 2;
                g_top2v[o] = V1;  g_top2i[o] = I1;
                g_top2v[o + 1] = V2; g_top2i[o + 1] = I2;
            }
        }
}

// ---------------- 4. merge: margin-based candidate set + fp64 refinement ----------------
__global__ void merge_refine_kernel(const float* __restrict__ z_real,  const float* __restrict__ z_imag,
                                    const float* __restrict__ ctx_real, const float* __restrict__ ctx_imag,
                                    const int*   __restrict__ prev_idx,
                                    const float* __restrict__ codebook, const float* __restrict__ adjacency,
                                    const float* __restrict__ gate_w,   const float* __restrict__ gate_b,
                                    float* __restrict__ out) {
    __shared__ int s_cand[8][MAXCAND];
    __shared__ int s_cnt[8];
    const int w = threadIdx.x >> 5;
    const int lane = threadIdx.x & 31;
    const int n = blockIdx.x * 8 + w;
    const float INF = __int_as_float(0x7f800000);

    if (lane == 0) s_cnt[w] = 0;
    __syncwarp();

    // pass 1: global computed min
    float v1 = INF; int i1 = 0x7fffffff;
    const size_t base = (size_t)n * (RECORDS * 2);
#pragma unroll
    for (int q = 0; q < 16; q++) {
        int e = lane + q * 32;
        float v = g_top2v[base + e];
        int ix  = g_top2i[base + e];
        if (v < v1 || (v == v1 && ix < i1)) { v1 = v; i1 = ix; }
    }
#pragma unroll
    for (int off = 16; off; off >>= 1) {
        float ov = __shfl_down_sync(0xffffffffu, v1, off);
        int   oi = __shfl_down_sync(0xffffffffu, i1, off);
        if (ov < v1 || (ov == v1 && oi < i1)) { v1 = ov; i1 = oi; }
    }
    float bv1 = __shfl_sync(0xffffffffu, v1, 0);
    int   bi1 = __shfl_sync(0xffffffffu, i1, 0);

    // pass 2: collect candidates within margin
    float thr = bv1 + MARGIN;
#pragma unroll
    for (int q = 0; q < 16; q++) {
        int e = lane + q * 32;
        float v = g_top2v[base + e];
        int ix  = g_top2i[base + e];
        if (v <= thr && ix != 0x7fffffff) {
            int pos = atomicAdd(&s_cnt[w], 1);
            if (pos < MAXCAND) s_cand[w][pos] = ix;
        }
    }
    __syncwarp();
    int count = s_cnt[w];
    if (count > MAXCAND) count = MAXCAND;

    int pick = bi1;
    if (count > 1) {
        double bestS = 1e300; int bestI = 0x7fffffff;
        const int p = prev_idx[n];
        for (int ci = 0; ci < count; ci++) {
            const int cc = s_cand[w][ci];
            double a0 = 0, a1 = 0, a2 = 0;
            for (int t = lane; t < D2; t += 32) {
                double zt = (t < 512) ? (double)z_real[(size_t)n * 512 + t]
                                      : (double)z_imag[(size_t)n * 512 + t - 512];
                double xt = (t < 512) ? (double)ctx_real[(size_t)n * 512 + t]
                                      : (double)ctx_imag[(size_t)n * 512 + t - 512];
                double cb = (double)codebook[(size_t)cc * D2 + t];
                double wv = (double)gate_w[(size_t)cc * D2 + t];
                a0 += cb * cb; a1 += zt * cb; a2 += xt * wv;
            }
            for (int o = 16; o; o >>= 1) {
                a0 += __shfl_down_sync(0xffffffffu, a0, o);
                a1 += __shfl_down_sync(0xffffffffu, a1, o);
                a2 += __shfl_down_sync(0xffffffffu, a2, o);
            }
            if (lane == 0) {
                double ad = (double)adjacency[(size_t)p * KSYM + cc];
                double gb = (double)gate_b[cc];
                double s = a0 - 2.0 * a1
                         - 0.8 * (1.0 / (1.0 + exp(-ad))) * (1.0 + 0.5 * tanh(a2 + gb));
                if (s < bestS || (s == bestS && cc < bestI)) { bestS = s; bestI = cc; }
            }
        }
        if (lane == 0) pick = bestI;
        pick = __shfl_sync(0xffffffffu, pick, 0);
    }
    if (lane == 0) {
        g_midx[n] = pick;
        out[MIDX_OFF + n] = (float)pick;
        atomicAdd(&g_counts[pick], 1);
    }
}

// ---------------- 5. z_q gather, embed_sum scatter, loss ----------------
__global__ void scatter_kernel(const float* __restrict__ z_real, const float* __restrict__ z_imag,
                               const float* __restrict__ codebook, float* __restrict__ out) {
    const int n = blockIdx.x;
    const int m = g_midx[n];
    const int tid = threadIdx.x;
    const int d0 = tid * 4;

    float4 c = *(const float4*)(codebook + (size_t)m * D2 + d0);
    float4 z;
    if (d0 < 512) z = *(const float4*)(z_real + (size_t)n * 512 + d0);
    else          z = *(const float4*)(z_imag + (size_t)n * 512 + d0 - 512);

    *(float4*)(out + ZQ_OFF + (size_t)n * D2 + d0) = c;

    float* ea = out + NEA_OFF + (size_t)m * D2 + d0;
    atomicAdd(ea + 0, 0.01f * z.x);
    atomicAdd(ea + 1, 0.01f * z.y);
    atomicAdd(ea + 2, 0.01f * z.z);
    atomicAdd(ea + 3, 0.01f * z.w);

    float dx = c.x - z.x, dy = c.y - z.y, dz = c.z - z.z, dw = c.w - z.w;
    float lsum = dx * dx + dy * dy + dz * dz + dw * dw;

    __shared__ float sh[256];
    sh[tid] = lsum; __syncthreads();
    for (int o = 128; o > 0; o >>= 1) { if (tid < o) sh[tid] += sh[tid + o]; __syncthreads(); }
    if (tid == 0) atomicAdd(&g_loss, (double)sh[0]);
}

// ---------------- 6a. cluster-size EMA, cs, loss ----------------
__global__ void finalize_a_kernel(const float* __restrict__ cluster_size, float* __restrict__ out) {
    const int tid = threadIdx.x;  // 1024 threads
    float ncs[8];
    float psum = 0.f;
#pragma unroll
    for (int q = 0; q < 8; q++) {
        int k = tid * 8 + q;
        float v = cluster_size[k] * 0.99f + 0.01f * (float)g_counts[k];
        ncs[q] = v;
        out[NCS_OFF + k] = v;
        psum += v;
    }
    __shared__ float sh[1024];
    sh[tid] = psum; __syncthreads();
    for (int o = 512; o > 0; o >>= 1) { if (tid < o) sh[tid] += sh[tid + o]; __syncthreads(); }
    float ntot = sh[0];
#pragma unroll
    for (int q = 0; q < 8; q++) {
        float cs = (ncs[q] + 1e-6f) / (ntot + (float)KSYM * 1e-6f) * ntot;
        g_cs[tid * 8 + q] = cs;
    }
    if (tid == 0) out[LOSS_OFF] = (float)(1.25 * g_loss / 16777216.0);
}

// ---------------- 6b. new_codebook = new_embed_avg / cs ----------------
__global__ void finalize_b_kernel(float* __restrict__ out) {
    size_t total = (size_t)KSYM * D2;
    size_t stride = (size_t)gridDim.x * blockDim.x;
    for (size_t i = (size_t)blockIdx.x * blockDim.x + threadIdx.x; i < total; i += stride) {
        int k = (int)(i >> 10);
        out[NCB_OFF + i] = out[NEA_OFF + i] / g_cs[k];
    }
}

// ---------------- entry ----------------
extern "C" void kernel_launch(void* const* d_in, const int* in_sizes, int n_in,
                              void* d_out, int out_size) {
    const float* z_real     = (const float*)d_in[0];
    const float* z_imag     = (const float*)d_in[1];
    const float* ctx_real   = (const float*)d_in[2];
    const float* ctx_imag   = (const float*)d_in[3];
    const int*   prev_idx   = (const int*)d_in[4];
    const float* codebook   = (const float*)d_in[5];
    const float* adjacency  = (const float*)d_in[6];
    const float* gate_w     = (const float*)d_in[7];
    const float* gate_b     = (const float*)d_in[8];
    const float* cluster_sz = (const float*)d_in[9];
    const float* embed_avg  = (const float*)d_in[10];
    float* out = (float*)d_out;

    cudaFuncSetAttribute(score_mma_kernel, cudaFuncAttributeMaxDynamicSharedMemorySize, SMEM_BYTES);

    perm_z_kernel<<<4096, 256>>>(z_real, z_imag);
    perm_cb_kernel<<<4096, 256>>>(codebook);
    perm_ctx_kernel<<<4096, 256>>>(ctx_real, ctx_imag);
    perm_gw_kernel<<<4096, 256>>>(gate_w);
    prep_cnorm_kernel<<<KSYM, 256>>>(codebook);
    init_kernel<<<8192, 256>>>(embed_avg, out);
    // blockIdx.x = column tile (fast) so codebook/gate_w stay L2-resident
    score_mma_kernel<<<dim3(KSYM / BN, N_ROWS / BM), 512, SMEM_BYTES>>>(
        prev_idx, adjacency, gate_b);
    merge_refine_kernel<<<N_ROWS / 8, 256>>>(z_real, z_imag, ctx_real, ctx_imag,
                                             prev_idx, codebook, adjacency, gate_w, gate_b, out);
    scatter_kernel<<<N_ROWS, 256>>>(z_real, z_imag, codebook, out);
    finalize_a_kernel<<<1, 1024>>>(cluster_sz, out);
    finalize_b_kernel<<<8192, 256>>>(out);
}

// round 9
// speedup vs baseline: 1.4990x; 1.4990x over previous
#include <cuda_runtime.h>
#include <cuda_fp16.h>
#include <math.h>
#include <stdint.h>

// ---------------- problem constants ----------------
#define N_ROWS 16384
#define D2     1024
#define KSYM   8192
#define BM     128            // rows per CTA (blockIdx.y)
#define BN     128            // symbol cols per CTA (blockIdx.x)
#define BK     64             // k per stage (two 32-k sub-chunks)
#define NCHUNK (D2 / BK)      // 16
#define RECORDS 256           // per-row top2 records = 64 col tiles * 4 warpN
#define MARGIN 1.0f
#define MAXCAND 24

// output packing (reference tuple order, flattened, float32)
#define ZQ_OFF   0ULL
#define LOSS_OFF 16777216ULL
#define MIDX_OFF 16777217ULL
#define NCB_OFF  16793601ULL
#define NCS_OFF  25182209ULL
#define NEA_OFF  25190401ULL

// smem stage layout: two fp16 segments, 128 rows x 128B each
#define SEG_Z   0
#define SEG_CB  16384
#define STAGE   32768
#define NSTAGE  3
#define SMEM_BYTES (NSTAGE * STAGE)   // 98304

// ---------------- scratch (device globals, no allocation) ----------------
__device__ float  g_cnorm[KSYM];
__device__ float  g_top2v[(size_t)N_ROWS * RECORDS * 2];
__device__ int    g_top2i[(size_t)N_ROWS * RECORDS * 2];
__device__ int    g_midx[N_ROWS];
__device__ int    g_counts[KSYM];
__device__ double g_loss;
__device__ float  g_cs[KSYM];
// pair-permuted fp16 operand copies (uint32 = 2 elems), 512 words/row
__device__ uint32_t g_zp[(size_t)N_ROWS * 512];
__device__ uint32_t g_cbp[(size_t)KSYM * 512];

// ---------------- helpers ----------------
__device__ __forceinline__ uint32_t smem_to_u32(const void* p) {
    uint32_t a;
    asm("{ .reg .u64 t; cvta.to.shared.u64 t, %1; cvt.u32.u64 %0, t; }" : "=r"(a) : "l"(p));
    return a;
}
__device__ __forceinline__ void cp16(uint32_t dst, const void* src) {
    asm volatile("cp.async.cg.shared.global [%0], [%1], 16;" :: "r"(dst), "l"(src));
}
__device__ __forceinline__ uint4 lds128(uint32_t addr) {
    uint4 v;
    asm volatile("ld.shared.v4.b32 {%0,%1,%2,%3}, [%4];"
        : "=r"(v.x), "=r"(v.y), "=r"(v.z), "=r"(v.w) : "r"(addr));
    return v;
}
__device__ __forceinline__ void mma_f16(float* d, const uint32_t* a, const uint32_t* b) {
    asm volatile(
        "mma.sync.aligned.m16n8k16.row.col.f32.f16.f16.f32 "
        "{%0,%1,%2,%3}, {%4,%5,%6,%7}, {%8,%9}, {%0,%1,%2,%3};"
        : "+f"(d[0]), "+f"(d[1]), "+f"(d[2]), "+f"(d[3])
        : "r"(a[0]), "r"(a[1]), "r"(a[2]), "r"(a[3]), "r"(b[0]), "r"(b[1]));
}
// pair p -> chunk c=p>>4 (32-k granule), pp=p&15, slot c*16 + (pp&3)*4 + (pp>>2)
__device__ __forceinline__ int pslot(int p) {
    int c = p >> 4, pp = p & 15;
    return c * 16 + (pp & 3) * 4 + (pp >> 2);
}

// ---------------- 0. permute+convert prep kernels ----------------
__global__ void perm_z_kernel(const float* __restrict__ zr, const float* __restrict__ zi) {
    size_t total = (size_t)N_ROWS * 512;
    size_t stride = (size_t)gridDim.x * blockDim.x;
    for (size_t i = (size_t)blockIdx.x * blockDim.x + threadIdx.x; i < total; i += stride) {
        int n = (int)(i >> 9), p = (int)(i & 511);
        int k = 2 * p;
        float a, b;
        if (k < 512) { a = zr[(size_t)n * 512 + k]; b = zr[(size_t)n * 512 + k + 1]; }
        else         { a = zi[(size_t)n * 512 + k - 512]; b = zi[(size_t)n * 512 + k - 511]; }
        __half2 h = __floats2half2_rn(a, b);
        uint32_t pack; *(__half2*)&pack = h;
        g_zp[(size_t)n * 512 + pslot(p)] = pack;
    }
}
__global__ void perm_cb_kernel(const float* __restrict__ cb) {
    size_t total = (size_t)KSYM * 512;
    size_t stride = (size_t)gridDim.x * blockDim.x;
    for (size_t i = (size_t)blockIdx.x * blockDim.x + threadIdx.x; i < total; i += stride) {
        int n = (int)(i >> 9), p = (int)(i & 511);
        __half2 h = __floats2half2_rn(cb[(size_t)n * 1024 + 2 * p], cb[(size_t)n * 1024 + 2 * p + 1]);
        uint32_t pack; *(__half2*)&pack = h;
        g_cbp[(size_t)n * 512 + pslot(p)] = pack;
    }
}

// ---------------- 1. codebook row norms (fp64 accumulate) ----------------
__global__ void prep_cnorm_kernel(const float* __restrict__ codebook) {
    int k = blockIdx.x;
    const float* row = codebook + (size_t)k * D2;
    double s = 0.0;
    for (int t = threadIdx.x; t < D2; t += 256) { double v = (double)row[t]; s += v * v; }
    __shared__ double sh[256];
    sh[threadIdx.x] = s; __syncthreads();
    for (int o = 128; o > 0; o >>= 1) { if (threadIdx.x < o) sh[threadIdx.x] += sh[threadIdx.x + o]; __syncthreads(); }
    if (threadIdx.x == 0) g_cnorm[k] = (float)sh[0];
}

// ---------------- 2. init ----------------
__global__ void init_kernel(const float* __restrict__ embed_avg, float* __restrict__ out) {
    size_t total = (size_t)KSYM * D2;
    size_t stride = (size_t)gridDim.x * blockDim.x;
    size_t j = (size_t)blockIdx.x * blockDim.x + threadIdx.x;
    for (size_t i = j; i < total; i += stride) out[NEA_OFF + i] = 0.99f * embed_avg[i];
    if (j < KSYM) g_counts[j] = 0;
    if (j == 0) g_loss = 0.0;
}

// ---------------- 3. fused dot-GEMM score kernel (fp16; gate term deferred) ----------------
// 512 threads, 16 warps: warp grid 4(M) x 4(N), warp tile 32x32, CTA tile 128x128.
// approx score s = cnorm - 2*dot - 0.8*sigmoid(adj); tanh term (|.|<0.4) resolved in refine.
__global__ __launch_bounds__(512, 1)
void score_mma_kernel(const int* __restrict__ prev_idx,
                      const float* __restrict__ adjacency) {
    extern __shared__ char smem[];
    const uint32_t sbu = smem_to_u32(smem);
    const int tid   = threadIdx.x;
    const int wid   = tid >> 5;
    const int lane  = tid & 31;
    const int g     = lane >> 2;
    const int tig   = lane & 3;
    const int warpM = wid >> 2;
    const int warpN = wid & 3;
    const int rowBase = blockIdx.y * BM;
    const int cbase   = blockIdx.x * BN;

    // ---- stage loader: 4 x 16B per thread (2 segs x 2 sub-chunks) ----
    auto load_stage = [&](int c, int buf) {
        const uint32_t bb = sbu + (uint32_t)buf * STAGE;
        int r = tid >> 2, qq = tid & 3;
#pragma unroll
        for (int sc = 0; sc < 2; sc++) {
            uint32_t so = (uint32_t)(r * 128 + sc * 64 + qq * 16);
            size_t gw = (size_t)(2 * c + sc) * 16 + qq * 4;
            cp16(bb + SEG_Z + so, g_zp + (size_t)(rowBase + r) * 512 + gw);
            cp16(bb + SEG_CB + so, g_cbp + (size_t)(cbase + r) * 512 + gw);
        }
        asm volatile("cp.async.commit_group;" ::: "memory");
    };

    float accd[2][4][4];
#pragma unroll
    for (int mt = 0; mt < 2; mt++)
#pragma unroll
        for (int nt = 0; nt < 4; nt++)
#pragma unroll
            for (int e = 0; e < 4; e++) accd[mt][nt][e] = 0.f;

    uint32_t aZ[4], aB[4];
#pragma unroll
    for (int s = 0; s < 4; s++) {
        aZ[s] = SEG_Z  + (uint32_t)(warpM * 32 + g + 8 * s) * 128 + tig * 16;
        aB[s] = SEG_CB + (uint32_t)(warpN * 32 + g + 8 * s) * 128 + tig * 16;
    }

    load_stage(0, 0);
    load_stage(1, 1);

    int buf = 0;
    for (int c = 0; c < NCHUNK; ++c) {
        if (c + 1 < NCHUNK) asm volatile("cp.async.wait_group 1;" ::: "memory");
        else                asm volatile("cp.async.wait_group 0;" ::: "memory");
        __syncthreads();
        if (c + 2 < NCHUNK) {
            int nb = buf + 2; if (nb >= NSTAGE) nb -= NSTAGE;
            load_stage(c + 2, nb);
        }
        const uint32_t bb = sbu + (uint32_t)buf * STAGE;

#pragma unroll
        for (int sc = 0; sc < 2; sc++) {
            const uint32_t o = (uint32_t)(sc * 64);
            uint32_t ax[4][4], bx[4][4];
#pragma unroll
            for (int s = 0; s < 4; s++) {
                uint4 vz = lds128(bb + aZ[s] + o);
                ax[s][0] = vz.x; ax[s][1] = vz.y; ax[s][2] = vz.z; ax[s][3] = vz.w;
                uint4 vb = lds128(bb + aB[s] + o);
                bx[s][0] = vb.x; bx[s][1] = vb.y; bx[s][2] = vb.z; bx[s][3] = vb.w;
            }
#pragma unroll
            for (int t = 0; t < 2; t++) {
                uint32_t af0[4] = {ax[0][2*t], ax[1][2*t], ax[0][2*t+1], ax[1][2*t+1]};
                uint32_t af1[4] = {ax[2][2*t], ax[3][2*t], ax[2][2*t+1], ax[3][2*t+1]};
#pragma unroll
                for (int nt = 0; nt < 4; nt++) {
                    uint32_t bf2[2] = {bx[nt][2*t], bx[nt][2*t+1]};
                    mma_f16(accd[0][nt], af0, bf2);
                    mma_f16(accd[1][nt], af1, bf2);
                }
            }
        }
        buf++; if (buf >= NSTAGE) buf = 0;
    }

    // ---- epilogue: approx bias + per-row top-2 ----
    float cnv[4][2];
#pragma unroll
    for (int nt = 0; nt < 4; nt++)
#pragma unroll
        for (int e = 0; e < 2; e++)
            cnv[nt][e] = g_cnorm[cbase + warpN * 32 + nt * 8 + 2 * tig + e];

    const float INF = __int_as_float(0x7f800000);
#pragma unroll
    for (int mt = 0; mt < 2; mt++)
#pragma unroll
        for (int hi = 0; hi < 2; hi++) {
            int rowg = rowBase + warpM * 32 + mt * 16 + hi * 8 + g;
            const float* adjr = adjacency + (size_t)prev_idx[rowg] * KSYM;
            float V1 = INF, V2 = INF;
            int   I1 = 0x7fffffff, I2 = 0x7fffffff;
#pragma unroll
            for (int nt = 0; nt < 4; nt++)
#pragma unroll
                for (int e = 0; e < 2; e++) {
                    int col = cbase + warpN * 32 + nt * 8 + 2 * tig + e;
                    float dot = accd[mt][nt][hi * 2 + e];
                    float adj = __ldg(adjr + col);
                    float sig = 1.f / (1.f + __expf(-adj));
                    float s = fmaf(-2.f, dot, cnv[nt][e]) - 0.8f * sig;
                    if (s < V1 || (s == V1 && col < I1)) { V2 = V1; I2 = I1; V1 = s; I1 = col; }
                    else if (s < V2 || (s == V2 && col < I2)) { V2 = s; I2 = col; }
                }
#pragma unroll
            for (int off = 1; off <= 2; off <<= 1) {
                float ov1 = __shfl_xor_sync(0xffffffffu, V1, off);
                int   oi1 = __shfl_xor_sync(0xffffffffu, I1, off);
                float ov2 = __shfl_xor_sync(0xffffffffu, V2, off);
                int   oi2 = __shfl_xor_sync(0xffffffffu, I2, off);
                if (ov1 < V1 || (ov1 == V1 && oi1 < I1)) {
                    float nv2; int ni2;
                    if (V1 < ov2 || (V1 == ov2 && I1 < oi2)) { nv2 = V1; ni2 = I1; }
                    else { nv2 = ov2; ni2 = oi2; }
                    V1 = ov1; I1 = oi1; V2 = nv2; I2 = ni2;
                } else if (ov1 < V2 || (ov1 == V2 && oi1 < I2)) {
                    V2 = ov1; I2 = oi1;
                }
            }
            if (tig == 0) {
                size_t o = ((size_t)rowg * RECORDS + blockIdx.x * 4 + warpN) * 2;
                g_top2v[o] = V1;  g_top2i[o] = I1;
                g_top2v[o + 1] = V2; g_top2i[o + 1] = I2;
            }
        }
}

// ---------------- 4. merge: margin candidate set + fp64 full-score refinement ----------------
__global__ void merge_refine_kernel(const float* __restrict__ z_real,  const float* __restrict__ z_imag,
                                    const float* __restrict__ ctx_real, const float* __restrict__ ctx_imag,
                                    const int*   __restrict__ prev_idx,
                                    const float* __restrict__ codebook, const float* __restrict__ adjacency,
                                    const float* __restrict__ gate_w,   const float* __restrict__ gate_b,
                                    float* __restrict__ out) {
    __shared__ int s_cand[8][MAXCAND];
    __shared__ int s_cnt[8];
    const int w = threadIdx.x >> 5;
    const int lane = threadIdx.x & 31;
    const int n = blockIdx.x * 8 + w;
    const float INF = __int_as_float(0x7f800000);

    if (lane == 0) s_cnt[w] = 0;
    __syncwarp();

    // pass 1: approx min
    float v1 = INF; int i1 = 0x7fffffff;
    const size_t base = (size_t)n * (RECORDS * 2);
#pragma unroll
    for (int q = 0; q < 16; q++) {
        int e = lane + q * 32;
        float v = g_top2v[base + e];
        int ix  = g_top2i[base + e];
        if (v < v1 || (v == v1 && ix < i1)) { v1 = v; i1 = ix; }
    }
#pragma unroll
    for (int off = 16; off; off >>= 1) {
        float ov = __shfl_down_sync(0xffffffffu, v1, off);
        int   oi = __shfl_down_sync(0xffffffffu, i1, off);
        if (ov < v1 || (ov == v1 && oi < i1)) { v1 = ov; i1 = oi; }
    }
    float bv1 = __shfl_sync(0xffffffffu, v1, 0);
    int   bi1 = __shfl_sync(0xffffffffu, i1, 0);

    // pass 2: candidates within margin (true argmin provably inside)
    float thr = bv1 + MARGIN;
#pragma unroll
    for (int q = 0; q < 16; q++) {
        int e = lane + q * 32;
        float v = g_top2v[base + e];
        int ix  = g_top2i[base + e];
        if (v <= thr && ix != 0x7fffffff) {
            int pos = atomicAdd(&s_cnt[w], 1);
            if (pos < MAXCAND) s_cand[w][pos] = ix;
        }
    }
    __syncwarp();
    int count = s_cnt[w];
    if (count > MAXCAND) count = MAXCAND;

    int pick = bi1;
    if (count > 1) {
        double bestS = 1e300; int bestI = 0x7fffffff;
        const int p = prev_idx[n];
        for (int ci = 0; ci < count; ci++) {
            const int cc = s_cand[w][ci];
            double a0 = 0, a1 = 0, a2 = 0;
            for (int t = lane; t < D2; t += 32) {
                double zt = (t < 512) ? (double)z_real[(size_t)n * 512 + t]
                                      : (double)z_imag[(size_t)n * 512 + t - 512];
                double xt = (t < 512) ? (double)ctx_real[(size_t)n * 512 + t]
                                      : (double)ctx_imag[(size_t)n * 512 + t - 512];
                double cb = (double)codebook[(size_t)cc * D2 + t];
                double wv = (double)gate_w[(size_t)cc * D2 + t];
                a0 += cb * cb; a1 += zt * cb; a2 += xt * wv;
            }
            for (int o = 16; o; o >>= 1) {
                a0 += __shfl_down_sync(0xffffffffu, a0, o);
                a1 += __shfl_down_sync(0xffffffffu, a1, o);
                a2 += __shfl_down_sync(0xffffffffu, a2, o);
            }
            if (lane == 0) {
                double ad = (double)adjacency[(size_t)p * KSYM + cc];
                double gb = (double)gate_b[cc];
                double s = a0 - 2.0 * a1
                         - 0.8 * (1.0 / (1.0 + exp(-ad))) * (1.0 + 0.5 * tanh(a2 + gb));
                if (s < bestS || (s == bestS && cc < bestI)) { bestS = s; bestI = cc; }
            }
        }
        if (lane == 0) pick = bestI;
        pick = __shfl_sync(0xffffffffu, pick, 0);
    }
    if (lane == 0) {
        g_midx[n] = pick;
        out[MIDX_OFF + n] = (float)pick;
        atomicAdd(&g_counts[pick], 1);
    }
}

// ---------------- 5. z_q gather, embed_sum scatter, loss ----------------
__global__ void scatter_kernel(const float* __restrict__ z_real, const float* __restrict__ z_imag,
                               const float* __restrict__ codebook, float* __restrict__ out) {
    const int n = blockIdx.x;
    const int m = g_midx[n];
    const int tid = threadIdx.x;
    const int d0 = tid * 4;

    float4 c = *(const float4*)(codebook + (size_t)m * D2 + d0);
    float4 z;
    if (d0 < 512) z = *(const float4*)(z_real + (size_t)n * 512 + d0);
    else          z = *(const float4*)(z_imag + (size_t)n * 512 + d0 - 512);

    *(float4*)(out + ZQ_OFF + (size_t)n * D2 + d0) = c;

    float* ea = out + NEA_OFF + (size_t)m * D2 + d0;
    atomicAdd(ea + 0, 0.01f * z.x);
    atomicAdd(ea + 1, 0.01f * z.y);
    atomicAdd(ea + 2, 0.01f * z.z);
    atomicAdd(ea + 3, 0.01f * z.w);

    float dx = c.x - z.x, dy = c.y - z.y, dz = c.z - z.z, dw = c.w - z.w;
    float lsum = dx * dx + dy * dy + dz * dz + dw * dw;

    __shared__ float sh[256];
    sh[tid] = lsum; __syncthreads();
    for (int o = 128; o > 0; o >>= 1) { if (tid < o) sh[tid] += sh[tid + o]; __syncthreads(); }
    if (tid == 0) atomicAdd(&g_loss, (double)sh[0]);
}

// ---------------- 6a. cluster-size EMA, cs, loss ----------------
__global__ void finalize_a_kernel(const float* __restrict__ cluster_size, float* __restrict__ out) {
    const int tid = threadIdx.x;  // 1024 threads
    float ncs[8];
    float psum = 0.f;
#pragma unroll
    for (int q = 0; q < 8; q++) {
        int k = tid * 8 + q;
        float v = cluster_size[k] * 0.99f + 0.01f * (float)g_counts[k];
        ncs[q] = v;
        out[NCS_OFF + k] = v;
        psum += v;
    }
    __shared__ float sh[1024];
    sh[tid] = psum; __syncthreads();
    for (int o = 512; o > 0; o >>= 1) { if (tid < o) sh[tid] += sh[tid + o]; __syncthreads(); }
    float ntot = sh[0];
#pragma unroll
    for (int q = 0; q < 8; q++) {
        float cs = (ncs[q] + 1e-6f) / (ntot + (float)KSYM * 1e-6f) * ntot;
        g_cs[tid * 8 + q] = cs;
    }
    if (tid == 0) out[LOSS_OFF] = (float)(1.25 * g_loss / 16777216.0);
}

// ---------------- 6b. new_codebook = new_embed_avg / cs ----------------
__global__ void finalize_b_kernel(float* __restrict__ out) {
    size_t total = (size_t)KSYM * D2;
    size_t stride = (size_t)gridDim.x * blockDim.x;
    for (size_t i = (size_t)blockIdx.x * blockDim.x + threadIdx.x; i < total; i += stride) {
        int k = (int)(i >> 10);
        out[NCB_OFF + i] = out[NEA_OFF + i] / g_cs[k];
    }
}

// ---------------- entry ----------------
extern "C" void kernel_launch(void* const* d_in, const int* in_sizes, int n_in,
                              void* d_out, int out_size) {
    const float* z_real     = (const float*)d_in[0];
    const float* z_imag     = (const float*)d_in[1];
    const float* ctx_real   = (const float*)d_in[2];
    const float* ctx_imag   = (const float*)d_in[3];
    const int*   prev_idx   = (const int*)d_in[4];
    const float* codebook   = (const float*)d_in[5];
    const float* adjacency  = (const float*)d_in[6];
    const float* gate_w     = (const float*)d_in[7];
    const float* gate_b     = (const float*)d_in[8];
    const float* cluster_sz = (const float*)d_in[9];
    const float* embed_avg  = (const float*)d_in[10];
    float* out = (float*)d_out;

    cudaFuncSetAttribute(score_mma_kernel, cudaFuncAttributeMaxDynamicSharedMemorySize, SMEM_BYTES);

    perm_z_kernel<<<4096, 256>>>(z_real, z_imag);
    perm_cb_kernel<<<4096, 256>>>(codebook);
    prep_cnorm_kernel<<<KSYM, 256>>>(codebook);
    init_kernel<<<8192, 256>>>(embed_avg, out);
    // blockIdx.x = column tile (fast) so codebook stays L2-resident
    score_mma_kernel<<<dim3(KSYM / BN, N_ROWS / BM), 512, SMEM_BYTES>>>(prev_idx, adjacency);
    merge_refine_kernel<<<N_ROWS / 8, 256>>>(z_real, z_imag, ctx_real, ctx_imag,
                                             prev_idx, codebook, adjacency, gate_w, gate_b, out);
    scatter_kernel<<<N_ROWS, 256>>>(z_real, z_imag, codebook, out);
    finalize_a_kernel<<<1, 1024>>>(cluster_sz, out);
    finalize_b_kernel<<<8192, 256>>>(out);
}

// round 10
// speedup vs baseline: 2.2589x; 1.5070x over previous
#include <cuda_runtime.h>
#include <cuda_fp16.h>
#include <math.h>
#include <stdint.h>

// ---------------- problem constants ----------------
#define N_ROWS 16384
#define D2     1024
#define KSYM   8192
#define BM     128            // rows per CTA (blockIdx.y)
#define BN     128            // symbol cols per CTA (blockIdx.x)
#define BK     64             // k per stage (two 32-k sub-chunks)
#define NCHUNK (D2 / BK)      // 16
#define RECORDS 256           // per-row top2 records = 64 col tiles * 4 warpN
#define MARGIN 1.5f
#define MAXCAND 24

// output packing (reference tuple order, flattened, float32)
#define ZQ_OFF   0ULL
#define LOSS_OFF 16777216ULL
#define MIDX_OFF 16777217ULL
#define NCB_OFF  16793601ULL
#define NCS_OFF  25182209ULL
#define NEA_OFF  25190401ULL

// smem stage layout: two fp16 segments, 128 rows x 128B each (parity-swizzled halves)
#define SEG_Z   0
#define SEG_CB  16384
#define STAGE   32768
#define NSTAGE  3
#define SMEM_BYTES (NSTAGE * STAGE)   // 98304

// ---------------- scratch (device globals, no allocation) ----------------
__device__ float  g_cnorm[KSYM];
__device__ float  g_top2v[(size_t)N_ROWS * RECORDS * 2];
__device__ int    g_top2i[(size_t)N_ROWS * RECORDS * 2];
__device__ int    g_midx[N_ROWS];
__device__ int    g_counts[KSYM];
__device__ double g_loss;
__device__ float  g_cs[KSYM];
// pair-permuted fp16 operand copies (uint32 = 2 elems), 512 words/row
__device__ uint32_t g_zp[(size_t)N_ROWS * 512];
__device__ uint32_t g_cbp[(size_t)KSYM * 512];

// ---------------- helpers ----------------
__device__ __forceinline__ uint32_t smem_to_u32(const void* p) {
    uint32_t a;
    asm("{ .reg .u64 t; cvta.to.shared.u64 t, %1; cvt.u32.u64 %0, t; }" : "=r"(a) : "l"(p));
    return a;
}
__device__ __forceinline__ void cp16(uint32_t dst, const void* src) {
    asm volatile("cp.async.cg.shared.global [%0], [%1], 16;" :: "r"(dst), "l"(src));
}
__device__ __forceinline__ uint4 lds128(uint32_t addr) {
    uint4 v;
    asm volatile("ld.shared.v4.b32 {%0,%1,%2,%3}, [%4];"
        : "=r"(v.x), "=r"(v.y), "=r"(v.z), "=r"(v.w) : "r"(addr));
    return v;
}
__device__ __forceinline__ void mma_f16(float* d, const uint32_t* a, const uint32_t* b) {
    asm volatile(
        "mma.sync.aligned.m16n8k16.row.col.f32.f16.f16.f32 "
        "{%0,%1,%2,%3}, {%4,%5,%6,%7}, {%8,%9}, {%0,%1,%2,%3};"
        : "+f"(d[0]), "+f"(d[1]), "+f"(d[2]), "+f"(d[3])
        : "r"(a[0]), "r"(a[1]), "r"(a[2]), "r"(a[3]), "r"(b[0]), "r"(b[1]));
}
// pair p -> chunk c=p>>4 (32-k granule), pp=p&15, slot c*16 + (pp&3)*4 + (pp>>2)
__device__ __forceinline__ int pslot(int p) {
    int c = p >> 4, pp = p & 15;
    return c * 16 + (pp & 3) * 4 + (pp >> 2);
}

// ---------------- 0. permute+convert prep kernels ----------------
__global__ void perm_z_kernel(const float* __restrict__ zr, const float* __restrict__ zi) {
    size_t total = (size_t)N_ROWS * 512;
    size_t stride = (size_t)gridDim.x * blockDim.x;
    for (size_t i = (size_t)blockIdx.x * blockDim.x + threadIdx.x; i < total; i += stride) {
        int n = (int)(i >> 9), p = (int)(i & 511);
        int k = 2 * p;
        float a, b;
        if (k < 512) { a = zr[(size_t)n * 512 + k]; b = zr[(size_t)n * 512 + k + 1]; }
        else         { a = zi[(size_t)n * 512 + k - 512]; b = zi[(size_t)n * 512 + k - 511]; }
        __half2 h = __floats2half2_rn(a, b);
        uint32_t pack; *(__half2*)&pack = h;
        g_zp[(size_t)n * 512 + pslot(p)] = pack;
    }
}
__global__ void perm_cb_kernel(const float* __restrict__ cb) {
    size_t total = (size_t)KSYM * 512;
    size_t stride = (size_t)gridDim.x * blockDim.x;
    for (size_t i = (size_t)blockIdx.x * blockDim.x + threadIdx.x; i < total; i += stride) {
        int n = (int)(i >> 9), p = (int)(i & 511);
        __half2 h = __floats2half2_rn(cb[(size_t)n * 1024 + 2 * p], cb[(size_t)n * 1024 + 2 * p + 1]);
        uint32_t pack; *(__half2*)&pack = h;
        g_cbp[(size_t)n * 512 + pslot(p)] = pack;
    }
}

// ---------------- 1. codebook row norms (fp64 accumulate) ----------------
__global__ void prep_cnorm_kernel(const float* __restrict__ codebook) {
    int k = blockIdx.x;
    const float* row = codebook + (size_t)k * D2;
    double s = 0.0;
    for (int t = threadIdx.x; t < D2; t += 256) { double v = (double)row[t]; s += v * v; }
    __shared__ double sh[256];
    sh[threadIdx.x] = s; __syncthreads();
    for (int o = 128; o > 0; o >>= 1) { if (threadIdx.x < o) sh[threadIdx.x] += sh[threadIdx.x + o]; __syncthreads(); }
    if (threadIdx.x == 0) g_cnorm[k] = (float)sh[0];
}

// ---------------- 2. init ----------------
__global__ void init_kernel(const float* __restrict__ embed_avg, float* __restrict__ out) {
    size_t total = (size_t)KSYM * D2;
    size_t stride = (size_t)gridDim.x * blockDim.x;
    size_t j = (size_t)blockIdx.x * blockDim.x + threadIdx.x;
    for (size_t i = j; i < total; i += stride) out[NEA_OFF + i] = 0.99f * embed_avg[i];
    if (j < KSYM) g_counts[j] = 0;
    if (j == 0) g_loss = 0.0;
}

// ---------------- 3. fused dot-GEMM score kernel (fp16; bias terms deferred) ----------------
// 512 threads, 16 warps: warp grid 4(M) x 4(N), warp tile 32x32, CTA tile 128x128.
// approx score s = cnorm - 2*dot; the bounded bias term (0..1.2) is resolved in refine.
__global__ __launch_bounds__(512, 1)
void score_mma_kernel() {
    extern __shared__ char smem[];
    const uint32_t sbu = smem_to_u32(smem);
    const int tid   = threadIdx.x;
    const int wid   = tid >> 5;
    const int lane  = tid & 31;
    const int g     = lane >> 2;
    const int tig   = lane & 3;
    const int warpM = wid >> 2;
    const int warpN = wid & 3;
    const int rowBase = blockIdx.y * BM;
    const int cbase   = blockIdx.x * BN;

    // ---- stage loader: 4 x 16B per thread (2 segs x 2 sub-chunks), parity-swizzled ----
    auto load_stage = [&](int c, int buf) {
        const uint32_t bb = sbu + (uint32_t)buf * STAGE;
        int r = tid >> 2, qq = tid & 3;
        const uint32_t px = (uint32_t)((r & 1) << 6);   // parity half-swap
#pragma unroll
        for (int sc = 0; sc < 2; sc++) {
            uint32_t so = (uint32_t)(r * 128 + (((uint32_t)(sc * 64)) ^ px) + qq * 16);
            size_t gw = (size_t)(2 * c + sc) * 16 + qq * 4;
            cp16(bb + SEG_Z + so, g_zp + (size_t)(rowBase + r) * 512 + gw);
            cp16(bb + SEG_CB + so, g_cbp + (size_t)(cbase + r) * 512 + gw);
        }
        asm volatile("cp.async.commit_group;" ::: "memory");
    };

    float accd[2][4][4];
#pragma unroll
    for (int mt = 0; mt < 2; mt++)
#pragma unroll
        for (int nt = 0; nt < 4; nt++)
#pragma unroll
            for (int e = 0; e < 4; e++) accd[mt][nt][e] = 0.f;

    // fragment bases (rows g+8s; parity of row = g&1, constant per thread)
    const uint32_t gx = (uint32_t)((g & 1) << 6);
    uint32_t aZ[4], aB[4];
#pragma unroll
    for (int s = 0; s < 4; s++) {
        aZ[s] = SEG_Z  + (uint32_t)(warpM * 32 + g + 8 * s) * 128 + tig * 16;
        aB[s] = SEG_CB + (uint32_t)(warpN * 32 + g + 8 * s) * 128 + tig * 16;
    }

    load_stage(0, 0);
    load_stage(1, 1);

    int buf = 0;
    for (int c = 0; c < NCHUNK; ++c) {
        if (c + 1 < NCHUNK) asm volatile("cp.async.wait_group 1;" ::: "memory");
        else                asm volatile("cp.async.wait_group 0;" ::: "memory");
        __syncthreads();
        if (c + 2 < NCHUNK) {
            int nb = buf + 2; if (nb >= NSTAGE) nb -= NSTAGE;
            load_stage(c + 2, nb);
        }
        const uint32_t bb = sbu + (uint32_t)buf * STAGE;

#pragma unroll
        for (int sc = 0; sc < 2; sc++) {
            const uint32_t o = ((uint32_t)(sc * 64)) ^ gx;
            uint32_t ax[4][4], bx[4][4];
#pragma unroll
            for (int s = 0; s < 4; s++) {
                uint4 vz = lds128(bb + aZ[s] + o);
                ax[s][0] = vz.x; ax[s][1] = vz.y; ax[s][2] = vz.z; ax[s][3] = vz.w;
                uint4 vb = lds128(bb + aB[s] + o);
                bx[s][0] = vb.x; bx[s][1] = vb.y; bx[s][2] = vb.z; bx[s][3] = vb.w;
            }
#pragma unroll
            for (int t = 0; t < 2; t++) {
                uint32_t af0[4] = {ax[0][2*t], ax[1][2*t], ax[0][2*t+1], ax[1][2*t+1]};
                uint32_t af1[4] = {ax[2][2*t], ax[3][2*t], ax[2][2*t+1], ax[3][2*t+1]};
#pragma unroll
                for (int nt = 0; nt < 4; nt++) {
                    uint32_t bf2[2] = {bx[nt][2*t], bx[nt][2*t+1]};
                    mma_f16(accd[0][nt], af0, bf2);
                    mma_f16(accd[1][nt], af1, bf2);
                }
            }
        }
        buf++; if (buf >= NSTAGE) buf = 0;
    }

    // ---- epilogue: approx score + per-row top-2 (pure register math) ----
    float cnv[4][2];
#pragma unroll
    for (int nt = 0; nt < 4; nt++)
#pragma unroll
        for (int e = 0; e < 2; e++)
            cnv[nt][e] = g_cnorm[cbase + warpN * 32 + nt * 8 + 2 * tig + e];

    const float INF = __int_as_float(0x7f800000);
#pragma unroll
    for (int mt = 0; mt < 2; mt++)
#pragma unroll
        for (int hi = 0; hi < 2; hi++) {
            int rowg = rowBase + warpM * 32 + mt * 16 + hi * 8 + g;
            float V1 = INF, V2 = INF;
            int   I1 = 0x7fffffff, I2 = 0x7fffffff;
#pragma unroll
            for (int nt = 0; nt < 4; nt++)
#pragma unroll
                for (int e = 0; e < 2; e++) {
                    int col = cbase + warpN * 32 + nt * 8 + 2 * tig + e;
                    float s = fmaf(-2.f, accd[mt][nt][hi * 2 + e], cnv[nt][e]);
                    if (s < V1 || (s == V1 && col < I1)) { V2 = V1; I2 = I1; V1 = s; I1 = col; }
                    else if (s < V2 || (s == V2 && col < I2)) { V2 = s; I2 = col; }
                }
#pragma unroll
            for (int off = 1; off <= 2; off <<= 1) {
                float ov1 = __shfl_xor_sync(0xffffffffu, V1, off);
                int   oi1 = __shfl_xor_sync(0xffffffffu, I1, off);
                float ov2 = __shfl_xor_sync(0xffffffffu, V2, off);
                int   oi2 = __shfl_xor_sync(0xffffffffu, I2, off);
                if (ov1 < V1 || (ov1 == V1 && oi1 < I1)) {
                    float nv2; int ni2;
                    if (V1 < ov2 || (V1 == ov2 && I1 < oi2)) { nv2 = V1; ni2 = I1; }
                    else { nv2 = ov2; ni2 = oi2; }
                    V1 = ov1; I1 = oi1; V2 = nv2; I2 = ni2;
                } else if (ov1 < V2 || (ov1 == V2 && oi1 < I2)) {
                    V2 = ov1; I2 = oi1;
                }
            }
            if (tig == 0) {
                size_t o = ((size_t)rowg * RECORDS + blockIdx.x * 4 + warpN) * 2;
                g_top2v[o] = V1;  g_top2i[o] = I1;
                g_top2v[o + 1] = V2; g_top2i[o + 1] = I2;
            }
        }
}

// ---------------- 4. merge: margin candidate set + fp64 full-score refinement ----------------
__global__ void merge_refine_kernel(const float* __restrict__ z_real,  const float* __restrict__ z_imag,
                                    const float* __restrict__ ctx_real, const float* __restrict__ ctx_imag,
                                    const int*   __restrict__ prev_idx,
                                    const float* __restrict__ codebook, const float* __restrict__ adjacency,
                                    const float* __restrict__ gate_w,   const float* __restrict__ gate_b,
                                    float* __restrict__ out) {
    __shared__ int s_cand[8][MAXCAND];
    __shared__ int s_cnt[8];
    const int w = threadIdx.x >> 5;
    const int lane = threadIdx.x & 31;
    const int n = blockIdx.x * 8 + w;
    const float INF = __int_as_float(0x7f800000);

    if (lane == 0) s_cnt[w] = 0;
    __syncwarp();

    // pass 1: approx min
    float v1 = INF; int i1 = 0x7fffffff;
    const size_t base = (size_t)n * (RECORDS * 2);
#pragma unroll
    for (int q = 0; q < 16; q++) {
        int e = lane + q * 32;
        float v = g_top2v[base + e];
        int ix  = g_top2i[base + e];
        if (v < v1 || (v == v1 && ix < i1)) { v1 = v; i1 = ix; }
    }
#pragma unroll
    for (int off = 16; off; off >>= 1) {
        float ov = __shfl_down_sync(0xffffffffu, v1, off);
        int   oi = __shfl_down_sync(0xffffffffu, i1, off);
        if (ov < v1 || (ov == v1 && oi < i1)) { v1 = ov; i1 = oi; }
    }
    float bv1 = __shfl_sync(0xffffffffu, v1, 0);
    int   bi1 = __shfl_sync(0xffffffffu, i1, 0);

    // pass 2: candidates within margin (true argmin provably inside)
    float thr = bv1 + MARGIN;
#pragma unroll
    for (int q = 0; q < 16; q++) {
        int e = lane + q * 32;
        float v = g_top2v[base + e];
        int ix  = g_top2i[base + e];
        if (v <= thr && ix != 0x7fffffff) {
            int pos = atomicAdd(&s_cnt[w], 1);
            if (pos < MAXCAND) s_cand[w][pos] = ix;
        }
    }
    __syncwarp();
    int count = s_cnt[w];
    if (count > MAXCAND) count = MAXCAND;

    int pick = bi1;
    if (count > 1) {
        double bestS = 1e300; int bestI = 0x7fffffff;
        const int p = prev_idx[n];
        for (int ci = 0; ci < count; ci++) {
            const int cc = s_cand[w][ci];
            double a0 = 0, a1 = 0, a2 = 0;
            for (int t = lane; t < D2; t += 32) {
                double zt = (t < 512) ? (double)z_real[(size_t)n * 512 + t]
                                      : (double)z_imag[(size_t)n * 512 + t - 512];
                double xt = (t < 512) ? (double)ctx_real[(size_t)n * 512 + t]
                                      : (double)ctx_imag[(size_t)n * 512 + t - 512];
                double cb = (double)codebook[(size_t)cc * D2 + t];
                double wv = (double)gate_w[(size_t)cc * D2 + t];
                a0 += cb * cb; a1 += zt * cb; a2 += xt * wv;
            }
            for (int o = 16; o; o >>= 1) {
                a0 += __shfl_down_sync(0xffffffffu, a0, o);
                a1 += __shfl_down_sync(0xffffffffu, a1, o);
                a2 += __shfl_down_sync(0xffffffffu, a2, o);
            }
            if (lane == 0) {
                double ad = (double)adjacency[(size_t)p * KSYM + cc];
                double gb = (double)gate_b[cc];
                double s = a0 - 2.0 * a1
                         - 0.8 * (1.0 / (1.0 + exp(-ad))) * (1.0 + 0.5 * tanh(a2 + gb));
                if (s < bestS || (s == bestS && cc < bestI)) { bestS = s; bestI = cc; }
            }
        }
        if (lane == 0) pick = bestI;
        pick = __shfl_sync(0xffffffffu, pick, 0);
    }
    if (lane == 0) {
        g_midx[n] = pick;
        out[MIDX_OFF + n] = (float)pick;
        atomicAdd(&g_counts[pick], 1);
    }
}

// ---------------- 5. z_q gather, embed_sum scatter, loss ----------------
__global__ void scatter_kernel(const float* __restrict__ z_real, const float* __restrict__ z_imag,
                               const float* __restrict__ codebook, float* __restrict__ out) {
    const int n = blockIdx.x;
    const int m = g_midx[n];
    const int tid = threadIdx.x;
    const int d0 = tid * 4;

    float4 c = *(const float4*)(codebook + (size_t)m * D2 + d0);
    float4 z;
    if (d0 < 512) z = *(const float4*)(z_real + (size_t)n * 512 + d0);
    else          z = *(const float4*)(z_imag + (size_t)n * 512 + d0 - 512);

    *(float4*)(out + ZQ_OFF + (size_t)n * D2 + d0) = c;

    float* ea = out + NEA_OFF + (size_t)m * D2 + d0;
    atomicAdd(ea + 0, 0.01f * z.x);
    atomicAdd(ea + 1, 0.01f * z.y);
    atomicAdd(ea + 2, 0.01f * z.z);
    atomicAdd(ea + 3, 0.01f * z.w);

    float dx = c.x - z.x, dy = c.y - z.y, dz = c.z - z.z, dw = c.w - z.w;
    float lsum = dx * dx + dy * dy + dz * dz + dw * dw;

    __shared__ float sh[256];
    sh[tid] = lsum; __syncthreads();
    for (int o = 128; o > 0; o >>= 1) { if (tid < o) sh[tid] += sh[tid + o]; __syncthreads(); }
    if (tid == 0) atomicAdd(&g_loss, (double)sh[0]);
}

// ---------------- 6a. cluster-size EMA, cs, loss ----------------
__global__ void finalize_a_kernel(const float* __restrict__ cluster_size, float* __restrict__ out) {
    const int tid = threadIdx.x;  // 1024 threads
    float ncs[8];
    float psum = 0.f;
#pragma unroll
    for (int q = 0; q < 8; q++) {
        int k = tid * 8 + q;
        float v = cluster_size[k] * 0.99f + 0.01f * (float)g_counts[k];
        ncs[q] = v;
        out[NCS_OFF + k] = v;
        psum += v;
    }
    __shared__ float sh[1024];
    sh[tid] = psum; __syncthreads();
    for (int o = 512; o > 0; o >>= 1) { if (tid < o) sh[tid] += sh[tid + o]; __syncthreads(); }
    float ntot = sh[0];
#pragma unroll
    for (int q = 0; q < 8; q++) {
        float cs = (ncs[q] + 1e-6f) / (ntot + (float)KSYM * 1e-6f) * ntot;
        g_cs[tid * 8 + q] = cs;
    }
    if (tid == 0) out[LOSS_OFF] = (float)(1.25 * g_loss / 16777216.0);
}

// ---------------- 6b. new_codebook = new_embed_avg / cs ----------------
__global__ void finalize_b_kernel(float* __restrict__ out) {
    size_t total = (size_t)KSYM * D2;
    size_t stride = (size_t)gridDim.x * blockDim.x;
    for (size_t i = (size_t)blockIdx.x * blockDim.x + threadIdx.x; i < total; i += stride) {
        int k = (int)(i >> 10);
        out[NCB_OFF + i] = out[NEA_OFF + i] / g_cs[k];
    }
}

// ---------------- entry ----------------
extern "C" void kernel_launch(void* const* d_in, const int* in_sizes, int n_in,
                              void* d_out, int out_size) {
    const float* z_real     = (const float*)d_in[0];
    const float* z_imag     = (const float*)d_in[1];
    const float* ctx_real   = (const float*)d_in[2];
    const float* ctx_imag   = (const float*)d_in[3];
    const int*   prev_idx   = (const int*)d_in[4];
    const float* codebook   = (const float*)d_in[5];
    const float* adjacency  = (const float*)d_in[6];
    const float* gate_w     = (const float*)d_in[7];
    const float* gate_b     = (const float*)d_in[8];
    const float* cluster_sz = (const float*)d_in[9];
    const float* embed_avg  = (const float*)d_in[10];
    float* out = (float*)d_out;

    cudaFuncSetAttribute(score_mma_kernel, cudaFuncAttributeMaxDynamicSharedMemorySize, SMEM_BYTES);

    perm_z_kernel<<<4096, 256>>>(z_real, z_imag);
    perm_cb_kernel<<<4096, 256>>>(codebook);
    prep_cnorm_kernel<<<KSYM, 256>>>(codebook);
    init_kernel<<<8192, 256>>>(embed_avg, out);
    // blockIdx.x = column tile (fast) so codebook stays L2-resident
    score_mma_kernel<<<dim3(KSYM / BN, N_ROWS / BM), 512, SMEM_BYTES>>>();
    merge_refine_kernel<<<N_ROWS / 8, 256>>>(z_real, z_imag, ctx_real, ctx_imag,
                                             prev_idx, codebook, adjacency, gate_w, gate_b, out);
    scatter_kernel<<<N_ROWS, 256>>>(z_real, z_imag, codebook, out);
    finalize_a_kernel<<<1, 1024>>>(cluster_sz, out);
    finalize_b_kernel<<<8192, 256>>>(out);
}